// round 7
// baseline (speedup 1.0000x reference)
#include <cuda_runtime.h>
#include <cuda_bf16.h>
#include <mma.h>
#include <cstdint>
#include <cstddef>

using namespace nvcuda;

#define BB   2
#define LL   512
#define HIN  1024
#define ENT  16
#define DD   50
#define TOT  850
#define PADN 896
#define NMASK 511
#define SCALE 0.14142135623730951f

// ---------------------------------------------------------------------------
// Scratch (device globals)
// ---------------------------------------------------------------------------
__device__ __nv_bfloat16 g_Xh[1024 * 1024];
__device__ __nv_bfloat16 g_Xl[1024 * 1024];
__device__ __nv_bfloat16 g_WhT[2 * PADN * HIN];   // [z][n][k]
__device__ __nv_bfloat16 g_WlT[2 * PADN * HIN];
__device__ float g_proj_s[BB * (ENT + 1) * LL * DD];
__device__ float g_proj_e[BB * (ENT + 1) * LL * DD];
__device__ float g_cd[BB * NMASK];
__device__ float g_fm[2][BB][LL * LL];            // k-split partial final_mask
__device__ float g_tcos[LL * (DD / 2)];
__device__ float g_tsin[LL * (DD / 2)];

// ---------------------------------------------------------------------------
// Prep kernels
// ---------------------------------------------------------------------------
__global__ void split_x(const float* __restrict__ X)
{
    int idx = blockIdx.x * blockDim.x + threadIdx.x;
    if (idx >= 1024 * 1024) return;
    float x = X[idx];
    __nv_bfloat16 h = __float2bfloat16(x);
    __nv_bfloat16 l = __float2bfloat16(x - __bfloat162float(h));
    g_Xh[idx] = h;
    g_Xl[idx] = l;
}

__global__ void split_wT(const float* __restrict__ W0, const float* __restrict__ W1)
{
    __shared__ __nv_bfloat16 th[32][33];
    __shared__ __nv_bfloat16 tl[32][33];
    const int z = blockIdx.z;
    const float* W = z ? W1 : W0;
    const int n0 = blockIdx.x * 32;
    const int k0 = blockIdx.y * 32;
    const int tx = threadIdx.x, ty = threadIdx.y;

    int n = n0 + tx, k = k0 + ty;
    float x = (n < TOT) ? W[(size_t)k * TOT + n] : 0.f;
    __nv_bfloat16 h = __float2bfloat16(x);
    __nv_bfloat16 l = __float2bfloat16(x - __bfloat162float(h));
    th[ty][tx] = h;
    tl[ty][tx] = l;
    __syncthreads();

    int on = n0 + ty, ok = k0 + tx;
    size_t oidx = (size_t)z * PADN * HIN + (size_t)on * HIN + ok;
    g_WhT[oidx] = th[tx][ty];
    g_WlT[oidx] = tl[tx][ty];
}

__global__ void trig_table()
{
    int idx = blockIdx.x * blockDim.x + threadIdx.x;
    if (idx >= LL * (DD / 2)) return;
    int l = idx / (DD / 2), t = idx - l * (DD / 2);
    double inv = exp(-((2.0 * t) / (double)DD) * log(10000.0));
    double ang = (double)l * inv;
    g_tcos[idx] = (float)cos(ang);
    g_tsin[idx] = (float)sin(ang);
}

// ---------------------------------------------------------------------------
// WMMA bf16 GEMM (unchanged — 72us known-good)
// ---------------------------------------------------------------------------
union GemmSmem {
    struct {
        __nv_bfloat16 Ah[128][40];
        __nv_bfloat16 Al[128][40];
        __nv_bfloat16 Bh[64][40];
        __nv_bfloat16 Bl[64][40];
    } t;
    float out[128][68];
};

__global__ __launch_bounds__(256) void gemm_wmma(
    const float* __restrict__ bias0, const float* __restrict__ bias1)
{
    __shared__ GemmSmem sm;

    const int z  = blockIdx.z;
    const int n0 = blockIdx.x * 64;
    const int m0 = blockIdx.y * 128;
    const float* bias = z ? bias1 : bias0;
    float* dst        = z ? g_proj_e : g_proj_s;

    const int tid = threadIdx.x;
    const int wid = tid >> 5;
    const int wr = wid >> 1;
    const int wc = wid & 1;

    const uint4* Xh4 = reinterpret_cast<const uint4*>(g_Xh);
    const uint4* Xl4 = reinterpret_cast<const uint4*>(g_Xl);
    const uint4* Bh4 = reinterpret_cast<const uint4*>(g_WhT) + (size_t)z * PADN * 128;
    const uint4* Bl4 = reinterpret_cast<const uint4*>(g_WlT) + (size_t)z * PADN * 128;

    wmma::fragment<wmma::accumulator, 16, 16, 16, float> c[2][2];
    #pragma unroll
    for (int i = 0; i < 2; i++)
        #pragma unroll
        for (int j = 0; j < 2; j++)
            wmma::fill_fragment(c[i][j], 0.f);

    for (int kc = 0; kc < HIN; kc += 32) {
        const int kc8 = kc >> 3;
        #pragma unroll
        for (int it = 0; it < 2; it++) {
            int u = it * 256 + tid;
            int row = u >> 2, c8 = u & 3;
            size_t gi = (size_t)(m0 + row) * 128 + kc8 + c8;
            *reinterpret_cast<uint4*>(&sm.t.Ah[row][c8 * 8]) = Xh4[gi];
            *reinterpret_cast<uint4*>(&sm.t.Al[row][c8 * 8]) = Xl4[gi];
        }
        {
            int row = tid >> 2, c8 = tid & 3;
            size_t gi = (size_t)(n0 + row) * 128 + kc8 + c8;
            *reinterpret_cast<uint4*>(&sm.t.Bh[row][c8 * 8]) = Bh4[gi];
            *reinterpret_cast<uint4*>(&sm.t.Bl[row][c8 * 8]) = Bl4[gi];
        }
        __syncthreads();

        #pragma unroll
        for (int ks = 0; ks < 32; ks += 16) {
            wmma::fragment<wmma::matrix_a, 16, 16, 16, __nv_bfloat16, wmma::row_major> ah[2], al[2];
            wmma::fragment<wmma::matrix_b, 16, 16, 16, __nv_bfloat16, wmma::col_major> bh[2], bl[2];
            #pragma unroll
            for (int i = 0; i < 2; i++) {
                wmma::load_matrix_sync(ah[i], &sm.t.Ah[wr * 32 + i * 16][ks], 40);
                wmma::load_matrix_sync(al[i], &sm.t.Al[wr * 32 + i * 16][ks], 40);
            }
            #pragma unroll
            for (int j = 0; j < 2; j++) {
                wmma::load_matrix_sync(bh[j], &sm.t.Bh[wc * 32 + j * 16][ks], 40);
                wmma::load_matrix_sync(bl[j], &sm.t.Bl[wc * 32 + j * 16][ks], 40);
            }
            #pragma unroll
            for (int i = 0; i < 2; i++)
                #pragma unroll
                for (int j = 0; j < 2; j++) {
                    wmma::mma_sync(c[i][j], ah[i], bh[j], c[i][j]);
                    wmma::mma_sync(c[i][j], ah[i], bl[j], c[i][j]);
                    wmma::mma_sync(c[i][j], al[i], bh[j], c[i][j]);
                }
        }
        __syncthreads();
    }

    #pragma unroll
    for (int i = 0; i < 2; i++)
        #pragma unroll
        for (int j = 0; j < 2; j++)
            wmma::store_matrix_sync(&sm.out[wr * 32 + i * 16][wc * 32 + j * 16],
                                    c[i][j], 68, wmma::mem_row_major);
    __syncthreads();

    for (int idx = tid; idx < 128 * 64; idx += 256) {
        int row = idx >> 6, col = idx & 63;
        int n = n0 + col;
        if (n < TOT) {
            int e = n / DD, d = n - e * DD;
            int m = m0 + row;
            int b = m >> 9, l = m & 511;
            dst[(((size_t)b * (ENT + 1) + e) * LL + l) * DD + d] =
                sm.out[row][col] + bias[n];
        }
    }
}

// ---------------------------------------------------------------------------
// RoPE apply (table lookup, e<16)
// ---------------------------------------------------------------------------
__global__ void rope_apply()
{
    int idx = blockIdx.x * blockDim.x + threadIdx.x;
    const int total = 2 * BB * ENT * LL * (DD / 2);
    if (idx >= total) return;

    int t = idx % (DD / 2); int r = idx / (DD / 2);
    int l = r % LL;          r /= LL;
    int e = r % ENT;         r /= ENT;
    int b = r % BB;          r /= BB;
    float* p = r ? g_proj_e : g_proj_s;

    float c = g_tcos[l * (DD / 2) + t];
    float s = g_tsin[l * (DD / 2) + t];

    size_t base = (((size_t)b * (ENT + 1) + e) * LL + l) * DD + 2 * t;
    float2 v = *reinterpret_cast<float2*>(&p[base]);
    float2 o;
    o.x = v.x * c - v.y * s;
    o.y = v.y * c + v.x * s;
    *reinterpret_cast<float2*>(&p[base]) = o;
}

// ---------------------------------------------------------------------------
// conj_diag — warp per (b,i), shfl reduce
// ---------------------------------------------------------------------------
__global__ __launch_bounds__(256) void conj_kernel()
{
    int wg = blockIdx.x * 8 + (threadIdx.x >> 5);
    int lane = threadIdx.x & 31;
    if (wg >= BB * NMASK) return;
    int b = wg / NMASK, i = wg - b * NMASK;
    const float* a = g_proj_s + (((size_t)b * (ENT + 1) + ENT) * LL + i) * DD;
    const float* c = g_proj_e + (((size_t)b * (ENT + 1) + ENT) * LL + (i + 1)) * DD;
    float s = 0.f;
    if (lane < DD)      s  = a[lane] * c[lane];
    if (lane + 32 < DD) s += a[lane + 32] * c[lane + 32];
    #pragma unroll
    for (int o = 16; o > 0; o >>= 1)
        s += __shfl_xor_sync(0xFFFFFFFFu, s, o);
    if (lane == 0) g_cd[wg] = s * SCALE;
}

// ---------------------------------------------------------------------------
// Mask-stream kernel: pure DRAM streaming, k-split 2.
// grid (8 j-tiles of 64, 32 i-tiles of 16, 2 k-splits), 256 threads.
// Thread = (i = ty, j-quad = tx*4). Writes partial sums to g_fm[ks].
// ---------------------------------------------------------------------------
__global__ __launch_bounds__(256) void mask_kernel(const float* __restrict__ mask)
{
    __shared__ float scd[BB * NMASK];
    const int tid = threadIdx.x;
    for (int k = tid; k < BB * NMASK; k += 256) scd[k] = g_cd[k];
    __syncthreads();

    const int tx = tid & 15, ty = tid >> 4;
    const int j0 = blockIdx.x * 64, i0 = blockIdx.y * 16;
    const int ks = blockIdx.z;
    const int i = i0 + ty, jq = j0 + tx * 4;

    const int kbeg = ks * 256;
    const int kend = ks ? NMASK : 256;     // [0,256) and [256,511)

    const float* mp = mask + (size_t)kbeg * (LL * LL) + (size_t)i * LL + jq;

    float4 a0 = make_float4(0.f, 0.f, 0.f, 0.f);
    float4 a1 = make_float4(0.f, 0.f, 0.f, 0.f);

    int k = kbeg;
    for (; k + 8 <= kend; k += 8) {
        float4 m[8];
        #pragma unroll
        for (int u = 0; u < 8; u++)
            m[u] = *reinterpret_cast<const float4*>(mp + (size_t)(k - kbeg + u) * (LL * LL));
        #pragma unroll
        for (int u = 0; u < 8; u++) {
            float c0 = scd[k + u], c1 = scd[NMASK + k + u];
            a0.x = fmaf(c0, m[u].x, a0.x); a0.y = fmaf(c0, m[u].y, a0.y);
            a0.z = fmaf(c0, m[u].z, a0.z); a0.w = fmaf(c0, m[u].w, a0.w);
            a1.x = fmaf(c1, m[u].x, a1.x); a1.y = fmaf(c1, m[u].y, a1.y);
            a1.z = fmaf(c1, m[u].z, a1.z); a1.w = fmaf(c1, m[u].w, a1.w);
        }
    }
    for (; k < kend; k++) {
        float4 m = *reinterpret_cast<const float4*>(mp + (size_t)(k - kbeg) * (LL * LL));
        float c0 = scd[k], c1 = scd[NMASK + k];
        a0.x = fmaf(c0, m.x, a0.x); a0.y = fmaf(c0, m.y, a0.y);
        a0.z = fmaf(c0, m.z, a0.z); a0.w = fmaf(c0, m.w, a0.w);
        a1.x = fmaf(c1, m.x, a1.x); a1.y = fmaf(c1, m.y, a1.y);
        a1.z = fmaf(c1, m.z, a1.z); a1.w = fmaf(c1, m.w, a1.w);
    }

    *reinterpret_cast<float4*>(&g_fm[ks][0][(size_t)i * LL + jq]) = a0;
    *reinterpret_cast<float4*>(&g_fm[ks][1][(size_t)i * LL + jq]) = a1;
}

// ---------------------------------------------------------------------------
// Scores kernel: out[b,i,j,e] = scale*q·k + fm0 + fm1
// grid (8 j-tiles of 64, 32 i-tiles of 16), 256 threads.
// ---------------------------------------------------------------------------
struct ScoreSmem {
    float skT[DD * 64];
    float sqT[DD * 16];
};

__global__ __launch_bounds__(256) void scores_kernel(float* __restrict__ out)
{
    __shared__ ScoreSmem sm;
    const int tid = threadIdx.x;
    const int tx = tid & 15, ty = tid >> 4;
    const int i0 = blockIdx.y * 16, j0 = blockIdx.x * 64;
    const int i = i0 + ty, jq = j0 + tx * 4;

    for (int b = 0; b < BB; b++) {
        float4 f0 = *reinterpret_cast<const float4*>(&g_fm[0][b][(size_t)i * LL + jq]);
        float4 f1 = *reinterpret_cast<const float4*>(&g_fm[1][b][(size_t)i * LL + jq]);
        const float am[4] = {f0.x + f1.x, f0.y + f1.y, f0.z + f1.z, f0.w + f1.w};

        float sreg[ENT][4];
        #pragma unroll 1
        for (int e = 0; e < ENT; e++) {
            __syncthreads();
            const float* qb = g_proj_s + (((size_t)b * (ENT + 1) + e) * LL + i0) * DD;
            const float* kb = g_proj_e + (((size_t)b * (ENT + 1) + e) * LL + j0) * DD;
            for (int x = tid; x < 16 * DD; x += 256) {
                int ii = x / DD, d = x - ii * DD;
                sm.sqT[d * 16 + ii] = qb[x];
            }
            for (int x = tid; x < 64 * DD; x += 256) {
                int jj = x / DD, d = x - jj * DD;
                sm.skT[d * 64 + jj] = kb[x];
            }
            __syncthreads();
            float r0 = 0.f, r1 = 0.f, r2 = 0.f, r3 = 0.f;
            #pragma unroll
            for (int d = 0; d < DD; d++) {
                float q = sm.sqT[d * 16 + ty];
                float4 kv = *reinterpret_cast<const float4*>(&sm.skT[d * 64 + tx * 4]);
                r0 = fmaf(q, kv.x, r0);
                r1 = fmaf(q, kv.y, r1);
                r2 = fmaf(q, kv.z, r2);
                r3 = fmaf(q, kv.w, r3);
            }
            sreg[e][0] = r0 * SCALE; sreg[e][1] = r1 * SCALE;
            sreg[e][2] = r2 * SCALE; sreg[e][3] = r3 * SCALE;
        }

        #pragma unroll
        for (int jj = 0; jj < 4; jj++) {
            float4* op = reinterpret_cast<float4*>(
                out + ((((size_t)b * LL + i) * LL + (jq + jj)) * ENT));
            #pragma unroll
            for (int v = 0; v < 4; v++)
                op[v] = make_float4(sreg[4 * v + 0][jj] + am[jj],
                                    sreg[4 * v + 1][jj] + am[jj],
                                    sreg[4 * v + 2][jj] + am[jj],
                                    sreg[4 * v + 3][jj] + am[jj]);
        }
    }
}

// ---------------------------------------------------------------------------
extern "C" void kernel_launch(void* const* d_in, const int* in_sizes, int n_in,
                              void* d_out, int out_size)
{
    const float* X    = (const float*)d_in[0];
    const float* mask = (const float*)d_in[1];
    const float* Ws   = (const float*)d_in[2];
    const float* bs   = (const float*)d_in[3];
    const float* We   = (const float*)d_in[4];
    const float* be   = (const float*)d_in[5];
    float* out        = (float*)d_out;

    split_x<<<(1024 * 1024 + 255) / 256, 256>>>(X);
    split_wT<<<dim3(PADN / 32, HIN / 32, 2), dim3(32, 32)>>>(Ws, We);
    trig_table<<<(LL * (DD / 2) + 255) / 256, 256>>>();

    gemm_wmma<<<dim3(PADN / 64, 1024 / 128, 2), 256>>>(bs, be);

    {
        const int total = 2 * BB * ENT * LL * (DD / 2);
        rope_apply<<<(total + 255) / 256, 256>>>();
    }
    conj_kernel<<<(BB * NMASK + 7) / 8, 256>>>();

    mask_kernel<<<dim3(8, 32, 2), 256>>>(mask);
    scores_kernel<<<dim3(8, 32), 256>>>(out);
}

// round 8
// speedup vs baseline: 1.3238x; 1.3238x over previous
#include <cuda_runtime.h>
#include <cuda_bf16.h>
#include <mma.h>
#include <cstdint>
#include <cstddef>

using namespace nvcuda;

#define BB   2
#define LL   512
#define HIN  1024
#define ENT  16
#define DD   50
#define TOT  850
#define PADN 896
#define NMASK 511
#define SCALE 0.14142135623730951f

// ---------------------------------------------------------------------------
// Scratch (device globals)
// ---------------------------------------------------------------------------
__device__ __nv_bfloat16 g_Xh[1024 * 1024];
__device__ __nv_bfloat16 g_Xl[1024 * 1024];
__device__ __nv_bfloat16 g_WhT[2 * PADN * HIN];   // [z][n][k]
__device__ __nv_bfloat16 g_WlT[2 * PADN * HIN];
__device__ float g_proj_s[BB * (ENT + 1) * LL * DD];
__device__ float g_proj_e[BB * (ENT + 1) * LL * DD];
__device__ float g_cd[BB * NMASK];
__device__ float g_tcos[LL * (DD / 2)];
__device__ float g_tsin[LL * (DD / 2)];

// ---------------------------------------------------------------------------
// Prep kernels
// ---------------------------------------------------------------------------
__global__ void split_x(const float* __restrict__ X)
{
    int idx = blockIdx.x * blockDim.x + threadIdx.x;
    if (idx >= 1024 * 1024) return;
    float x = X[idx];
    __nv_bfloat16 h = __float2bfloat16(x);
    __nv_bfloat16 l = __float2bfloat16(x - __bfloat162float(h));
    g_Xh[idx] = h;
    g_Xl[idx] = l;
}

__global__ void split_wT(const float* __restrict__ W0, const float* __restrict__ W1)
{
    __shared__ __nv_bfloat16 th[32][33];
    __shared__ __nv_bfloat16 tl[32][33];
    const int z = blockIdx.z;
    const float* W = z ? W1 : W0;
    const int n0 = blockIdx.x * 32;
    const int k0 = blockIdx.y * 32;
    const int tx = threadIdx.x, ty = threadIdx.y;

    int n = n0 + tx, k = k0 + ty;
    float x = (n < TOT) ? W[(size_t)k * TOT + n] : 0.f;
    __nv_bfloat16 h = __float2bfloat16(x);
    __nv_bfloat16 l = __float2bfloat16(x - __bfloat162float(h));
    th[ty][tx] = h;
    tl[ty][tx] = l;
    __syncthreads();

    int on = n0 + ty, ok = k0 + tx;
    size_t oidx = (size_t)z * PADN * HIN + (size_t)on * HIN + ok;
    g_WhT[oidx] = th[tx][ty];
    g_WlT[oidx] = tl[tx][ty];
}

__global__ void trig_table()
{
    int idx = blockIdx.x * blockDim.x + threadIdx.x;
    if (idx >= LL * (DD / 2)) return;
    int l = idx / (DD / 2), t = idx - l * (DD / 2);
    double inv = exp(-((2.0 * t) / (double)DD) * log(10000.0));
    double ang = (double)l * inv;
    g_tcos[idx] = (float)cos(ang);
    g_tsin[idx] = (float)sin(ang);
}

// ---------------------------------------------------------------------------
// WMMA bf16 GEMM (unchanged — 72us measured)
// ---------------------------------------------------------------------------
union GemmSmem {
    struct {
        __nv_bfloat16 Ah[128][40];
        __nv_bfloat16 Al[128][40];
        __nv_bfloat16 Bh[64][40];
        __nv_bfloat16 Bl[64][40];
    } t;
    float out[128][68];
};

__global__ __launch_bounds__(256) void gemm_wmma(
    const float* __restrict__ bias0, const float* __restrict__ bias1)
{
    __shared__ GemmSmem sm;

    const int z  = blockIdx.z;
    const int n0 = blockIdx.x * 64;
    const int m0 = blockIdx.y * 128;
    const float* bias = z ? bias1 : bias0;
    float* dst        = z ? g_proj_e : g_proj_s;

    const int tid = threadIdx.x;
    const int wid = tid >> 5;
    const int wr = wid >> 1;
    const int wc = wid & 1;

    const uint4* Xh4 = reinterpret_cast<const uint4*>(g_Xh);
    const uint4* Xl4 = reinterpret_cast<const uint4*>(g_Xl);
    const uint4* Bh4 = reinterpret_cast<const uint4*>(g_WhT) + (size_t)z * PADN * 128;
    const uint4* Bl4 = reinterpret_cast<const uint4*>(g_WlT) + (size_t)z * PADN * 128;

    wmma::fragment<wmma::accumulator, 16, 16, 16, float> c[2][2];
    #pragma unroll
    for (int i = 0; i < 2; i++)
        #pragma unroll
        for (int j = 0; j < 2; j++)
            wmma::fill_fragment(c[i][j], 0.f);

    for (int kc = 0; kc < HIN; kc += 32) {
        const int kc8 = kc >> 3;
        #pragma unroll
        for (int it = 0; it < 2; it++) {
            int u = it * 256 + tid;
            int row = u >> 2, c8 = u & 3;
            size_t gi = (size_t)(m0 + row) * 128 + kc8 + c8;
            *reinterpret_cast<uint4*>(&sm.t.Ah[row][c8 * 8]) = Xh4[gi];
            *reinterpret_cast<uint4*>(&sm.t.Al[row][c8 * 8]) = Xl4[gi];
        }
        {
            int row = tid >> 2, c8 = tid & 3;
            size_t gi = (size_t)(n0 + row) * 128 + kc8 + c8;
            *reinterpret_cast<uint4*>(&sm.t.Bh[row][c8 * 8]) = Bh4[gi];
            *reinterpret_cast<uint4*>(&sm.t.Bl[row][c8 * 8]) = Bl4[gi];
        }
        __syncthreads();

        #pragma unroll
        for (int ks = 0; ks < 32; ks += 16) {
            wmma::fragment<wmma::matrix_a, 16, 16, 16, __nv_bfloat16, wmma::row_major> ah[2], al[2];
            wmma::fragment<wmma::matrix_b, 16, 16, 16, __nv_bfloat16, wmma::col_major> bh[2], bl[2];
            #pragma unroll
            for (int i = 0; i < 2; i++) {
                wmma::load_matrix_sync(ah[i], &sm.t.Ah[wr * 32 + i * 16][ks], 40);
                wmma::load_matrix_sync(al[i], &sm.t.Al[wr * 32 + i * 16][ks], 40);
            }
            #pragma unroll
            for (int j = 0; j < 2; j++) {
                wmma::load_matrix_sync(bh[j], &sm.t.Bh[wc * 32 + j * 16][ks], 40);
                wmma::load_matrix_sync(bl[j], &sm.t.Bl[wc * 32 + j * 16][ks], 40);
            }
            #pragma unroll
            for (int i = 0; i < 2; i++)
                #pragma unroll
                for (int j = 0; j < 2; j++) {
                    wmma::mma_sync(c[i][j], ah[i], bh[j], c[i][j]);
                    wmma::mma_sync(c[i][j], ah[i], bl[j], c[i][j]);
                    wmma::mma_sync(c[i][j], al[i], bh[j], c[i][j]);
                }
        }
        __syncthreads();
    }

    #pragma unroll
    for (int i = 0; i < 2; i++)
        #pragma unroll
        for (int j = 0; j < 2; j++)
            wmma::store_matrix_sync(&sm.out[wr * 32 + i * 16][wc * 32 + j * 16],
                                    c[i][j], 68, wmma::mem_row_major);
    __syncthreads();

    for (int idx = tid; idx < 128 * 64; idx += 256) {
        int row = idx >> 6, col = idx & 63;
        int n = n0 + col;
        if (n < TOT) {
            int e = n / DD, d = n - e * DD;
            int m = m0 + row;
            int b = m >> 9, l = m & 511;
            dst[(((size_t)b * (ENT + 1) + e) * LL + l) * DD + d] =
                sm.out[row][col] + bias[n];
        }
    }
}

// ---------------------------------------------------------------------------
// RoPE apply (table lookup, e<16)
// ---------------------------------------------------------------------------
__global__ void rope_apply()
{
    int idx = blockIdx.x * blockDim.x + threadIdx.x;
    const int total = 2 * BB * ENT * LL * (DD / 2);
    if (idx >= total) return;

    int t = idx % (DD / 2); int r = idx / (DD / 2);
    int l = r % LL;          r /= LL;
    int e = r % ENT;         r /= ENT;
    int b = r % BB;          r /= BB;
    float* p = r ? g_proj_e : g_proj_s;

    float c = g_tcos[l * (DD / 2) + t];
    float s = g_tsin[l * (DD / 2) + t];

    size_t base = (((size_t)b * (ENT + 1) + e) * LL + l) * DD + 2 * t;
    float2 v = *reinterpret_cast<float2*>(&p[base]);
    float2 o;
    o.x = v.x * c - v.y * s;
    o.y = v.y * c + v.x * s;
    *reinterpret_cast<float2*>(&p[base]) = o;
}

// ---------------------------------------------------------------------------
// conj_diag — warp per (b,i), shfl reduce
// ---------------------------------------------------------------------------
__global__ __launch_bounds__(256) void conj_kernel()
{
    int wg = blockIdx.x * 8 + (threadIdx.x >> 5);
    int lane = threadIdx.x & 31;
    if (wg >= BB * NMASK) return;
    int b = wg / NMASK, i = wg - b * NMASK;
    const float* a = g_proj_s + (((size_t)b * (ENT + 1) + ENT) * LL + i) * DD;
    const float* c = g_proj_e + (((size_t)b * (ENT + 1) + ENT) * LL + (i + 1)) * DD;
    float s = 0.f;
    if (lane < DD)      s  = a[lane] * c[lane];
    if (lane + 32 < DD) s += a[lane + 32] * c[lane + 32];
    #pragma unroll
    for (int o = 16; o > 0; o >>= 1)
        s += __shfl_xor_sync(0xFFFFFFFFu, s, o);
    if (lane == 0) g_cd[wg] = s * SCALE;
}

// ---------------------------------------------------------------------------
// Fused mask-reduction + scores — EXACT round-1 structure (194.8us measured):
// 16x16 (i,j) tile per 256-thread block, 1024 blocks, scalar mask loads,
// 32 regs, occ ~80%. Mask first, then scores, per-thread 16-e sreg.
// ---------------------------------------------------------------------------
__global__ __launch_bounds__(256) void fused_kernel(
    const float* __restrict__ mask, float* __restrict__ out)
{
    __shared__ float scd[BB * NMASK];     // 1022
    __shared__ float sq[16 * DD];         // 800
    __shared__ float sk[16 * DD];

    const int tid = threadIdx.x;
    const int tx = tid & 15;   // j offset
    const int ty = tid >> 4;   // i offset

    for (int k = tid; k < BB * NMASK; k += 256) scd[k] = g_cd[k];

    const int i0 = blockIdx.y * 16, j0 = blockIdx.x * 16;
    const int i = i0 + ty, j = j0 + tx;
    const float* mp = mask + (size_t)i * LL + j;

    __syncthreads();

    // ---- mask reduction: 511 strided loads, unrolled x8 for MLP ----
    float a0 = 0.f, a1 = 0.f;
    int k = 0;
    for (; k + 8 <= NMASK; k += 8) {
        float m[8];
        #pragma unroll
        for (int u = 0; u < 8; u++) m[u] = mp[(size_t)(k + u) * (LL * LL)];
        #pragma unroll
        for (int u = 0; u < 8; u++) {
            a0 = fmaf(scd[k + u],          m[u], a0);
            a1 = fmaf(scd[NMASK + k + u],  m[u], a1);
        }
    }
    for (; k < NMASK; k++) {
        float m = mp[(size_t)k * (LL * LL)];
        a0 = fmaf(scd[k],         m, a0);
        a1 = fmaf(scd[NMASK + k], m, a1);
    }

    // ---- scores + epilogue ----
    for (int b = 0; b < BB; b++) {
        float sreg[ENT];
        const float amask = b ? a1 : a0;
        for (int e = 0; e < ENT; e++) {
            __syncthreads();
            const float* qb = g_proj_s + (((size_t)b * (ENT + 1) + e) * LL + i0) * DD;
            const float* kb = g_proj_e + (((size_t)b * (ENT + 1) + e) * LL + j0) * DD;
            for (int x = tid; x < 16 * DD; x += 256) {
                sq[x] = qb[x];   // tile rows are contiguous (stride DD)
                sk[x] = kb[x];
            }
            __syncthreads();
            float dot = 0.f;
            #pragma unroll
            for (int d = 0; d < DD; d++)
                dot = fmaf(sq[ty * DD + d], sk[tx * DD + d], dot);
            sreg[e] = dot * SCALE + amask;
        }
        // 16 contiguous e-values -> 4x float4 coalesced store
        float4* op = reinterpret_cast<float4*>(
            out + ((((size_t)b * LL + i) * LL + j) * ENT));
        #pragma unroll
        for (int v = 0; v < 4; v++)
            op[v] = make_float4(sreg[4 * v], sreg[4 * v + 1],
                                sreg[4 * v + 2], sreg[4 * v + 3]);
    }
}

// ---------------------------------------------------------------------------
extern "C" void kernel_launch(void* const* d_in, const int* in_sizes, int n_in,
                              void* d_out, int out_size)
{
    const float* X    = (const float*)d_in[0];
    const float* mask = (const float*)d_in[1];
    const float* Ws   = (const float*)d_in[2];
    const float* bs   = (const float*)d_in[3];
    const float* We   = (const float*)d_in[4];
    const float* be   = (const float*)d_in[5];
    float* out        = (float*)d_out;

    split_x<<<(1024 * 1024 + 255) / 256, 256>>>(X);
    split_wT<<<dim3(PADN / 32, HIN / 32, 2), dim3(32, 32)>>>(Ws, We);
    trig_table<<<(LL * (DD / 2) + 255) / 256, 256>>>();

    gemm_wmma<<<dim3(PADN / 64, 1024 / 128, 2), 256>>>(bs, be);

    {
        const int total = 2 * BB * ENT * LL * (DD / 2);
        rope_apply<<<(total + 255) / 256, 256>>>();
    }
    conj_kernel<<<(BB * NMASK + 7) / 8, 256>>>();

    fused_kernel<<<dim3(LL / 16, LL / 16), 256>>>(mask, out);
}